// round 14
// baseline (speedup 1.0000x reference)
#include <cuda_runtime.h>
#include <cuda_bf16.h>
#include <cstdint>

#define INC   64
#define DDIM  24
#define BATCH 16
#define DSP   (DDIM*DDIM*DDIM)      // 13824
#define NPOS  (BATCH*DSP)           // 221184
#define ODIM  47

// Collapsed-x array: C[b][g=wz*3+wy (9)][zh 26][yh 26][qx 24][par 2]
// z/y halo never written -> stays zero (.bss init).
#define CROW  48                    // 24 qx * 2 par
#define CSL   (26*CROW)             // 1248
#define CGRID (26*CSL)              // 32448 floats per (b,g)
#define CTOT  ((size_t)BATCH * 9 * CGRID)   // ~18.7 MB

__device__ float g_C[CTOT];

// ---------- helpers ----------
__device__ __forceinline__ uint32_t smem_u32(const void* p) {
    uint32_t a;
    asm("{ .reg .u64 t; cvta.to.shared.u64 t, %1; cvt.u32.u64 %0, t; }"
        : "=r"(a) : "l"(p));
    return a;
}
__device__ __forceinline__ uint32_t pack_bf(__nv_bfloat16 lo, __nv_bfloat16 hi) {
    return (uint32_t)__bfloat16_as_ushort(lo) | ((uint32_t)__bfloat16_as_ushort(hi) << 16);
}
__device__ __forceinline__ void ldsm_x4_t(uint32_t r[4], uint32_t addr) {
    asm volatile("ldmatrix.sync.aligned.m8n8.x4.trans.shared.b16 {%0,%1,%2,%3}, [%4];"
                 : "=r"(r[0]), "=r"(r[1]), "=r"(r[2]), "=r"(r[3]) : "r"(addr));
}
__device__ __forceinline__ void mma_bf16(float d[4], const uint32_t a[4],
                                         const uint32_t b0, const uint32_t b1) {
    asm volatile(
        "mma.sync.aligned.m16n8k16.row.col.f32.bf16.bf16.f32 "
        "{%0,%1,%2,%3}, {%4,%5,%6,%7}, {%8,%9}, {%0,%1,%2,%3};"
        : "+f"(d[0]), "+f"(d[1]), "+f"(d[2]), "+f"(d[3])
        : "r"(a[0]), "r"(a[1]), "r"(a[2]), "r"(a[3]), "r"(b0), "r"(b1));
}

// ============================================================
// Pass 1: HMMA taps + in-smem x-collapse.
// CTA = 128 thr, 288 positions (3 chunks of 96 = 4 full x-rows each).
// Per chunk: stage A splits (k-major, swizzled) -> 6 m16 tiles of
// m16n8k16 MMAs (3-term bf16 split) -> D to smem -> x-collapse ->
// C[g][z][y][qx][par] float2 stores.
// ============================================================
__global__ void __launch_bounds__(128, 3)
conv_pass1(const float* __restrict__ x, const float* __restrict__ w) {
    __shared__ __align__(16) char sA1[64 * 256];   // A1 split [k64][m96 pad]
    __shared__ __align__(16) char sA2[64 * 256];   // A2 split
    __shared__ float sD[96 * 29];                  // D[m][tap], stride 29
    const uint32_t sb1 = smem_u32(sA1);
    const uint32_t sb2 = smem_u32(sA2);

    const int tid  = threadIdx.x;
    const int lane = tid & 31;
    const int wid  = tid >> 5;

    // ---- W fragments (verified R12 layout): bw[nt][j][r] ----
    uint32_t bw1[4][4][2], bw2[4][4][2];
    {
        const int n = lane >> 2;
#pragma unroll
        for (int nt = 0; nt < 4; nt++) {
            const int ng = nt * 8 + n;
            const bool nok = ng < 27;
#pragma unroll
            for (int j = 0; j < 4; j++) {
#pragma unroll
                for (int r = 0; r < 2; r++) {
                    const int c0 = j * 16 + (lane & 3) * 2 + r * 8;
                    const float va = nok ? __ldg(w + c0 * 1728 + ng) : 0.0f;
                    const float vb = nok ? __ldg(w + (c0 + 1) * 1728 + ng) : 0.0f;
                    const __nv_bfloat16 a1 = __float2bfloat16(va);
                    const __nv_bfloat16 a2 = __float2bfloat16(va - __bfloat162float(a1));
                    const __nv_bfloat16 b1 = __float2bfloat16(vb);
                    const __nv_bfloat16 b2 = __float2bfloat16(vb - __bfloat162float(b1));
                    bw1[nt][j][r] = pack_bf(a1, b1);
                    bw2[nt][j][r] = pack_bf(a2, b2);
                }
            }
        }
    }

    const int p0  = blockIdx.x * 288;        // grid 768; 288 | 13824
    const int b   = p0 / DSP;
    const int spb = p0 - b * DSP;
    const float* __restrict__ xb0 = x + (size_t)b * INC * DSP;
    float* __restrict__ Cb0 = g_C + (size_t)b * 9 * CGRID;

    for (int chunk = 0; chunk < 3; chunk++) {
        const int sp0 = spb + chunk * 96;    // multiple of 96 -> row-complete
        __syncthreads();                     // sD readers done before re-stage

        // ---- stage A: 3072 float2-pairs: c = i/48, m pair = i%48 ----
        const float* __restrict__ xb = xb0 + sp0;
#pragma unroll 4
        for (int it = 0; it < 24; it++) {
            const int i  = it * 128 + tid;
            const int c  = i / 48;
            const int m0 = (i % 48) * 2;
            const float2 xv = __ldg((const float2*)(xb + (size_t)c * DSP + m0));
            const __nv_bfloat16 h1a = __float2bfloat16(xv.x);
            const __nv_bfloat16 h2a = __float2bfloat16(xv.x - __bfloat162float(h1a));
            const __nv_bfloat16 h1b = __float2bfloat16(xv.y);
            const __nv_bfloat16 h2b = __float2bfloat16(xv.y - __bfloat162float(h1b));
            const int off = c * 256 + ((((m0 >> 3) ^ (c & 7)) << 4)) + ((m0 & 7) * 2);
            *(uint32_t*)(sA1 + off) = pack_bf(h1a, h1b);
            *(uint32_t*)(sA2 + off) = pack_bf(h2a, h2b);
        }
        __syncthreads();

        // ---- MMA: 6 m16 tiles; warp wid does tiles wid, wid+4 ----
        for (int ti = wid; ti < 6; ti += 4) {
            const int mb = ti * 16;
            uint32_t fa1[4][4], fa2[4][4];
            const int sub = lane >> 3;
            const int mc  = mb + ((sub & 1) ? 8 : 0);
#pragma unroll
            for (int j = 0; j < 4; j++) {
                const int kr = j * 16 + ((sub & 2) ? 8 : 0) + (lane & 7);
                const uint32_t off = (uint32_t)(kr * 256 + (((mc >> 3) ^ (kr & 7)) << 4));
                ldsm_x4_t(fa1[j], sb1 + off);
                ldsm_x4_t(fa2[j], sb2 + off);
            }
            const int r0 = mb + (lane >> 2);
#pragma unroll
            for (int nt = 0; nt < 4; nt++) {
                float d[4] = {0.f, 0.f, 0.f, 0.f};
#pragma unroll
                for (int j = 0; j < 4; j++) mma_bf16(d, fa1[j], bw1[nt][j][0], bw1[nt][j][1]);
#pragma unroll
                for (int j = 0; j < 4; j++) mma_bf16(d, fa1[j], bw2[nt][j][0], bw2[nt][j][1]);
#pragma unroll
                for (int j = 0; j < 4; j++) mma_bf16(d, fa2[j], bw1[nt][j][0], bw1[nt][j][1]);

                const int t0 = nt * 8 + (lane & 3) * 2;
                const int t1 = t0 + 1;
                if (t0 < 27) { sD[r0 * 29 + t0] = d[0]; sD[(r0 + 8) * 29 + t0] = d[2]; }
                if (t1 < 27) { sD[r0 * 29 + t1] = d[1]; sD[(r0 + 8) * 29 + t1] = d[3]; }
            }
        }
        __syncthreads();

        // ---- x-collapse: thread m<96 -> E/O per zy-group g ----
        if (tid < 96) {
            const int m  = tid;
            const int sp = sp0 + m;
            const int xq = m % 24;
            const int z  = sp / 576;
            const int rr = sp - z * 576;
            const int y  = rr / 24;
            const float* Do = sD + m * 29;
            const float* Dl = sD + (m - 1) * 29;
            const float* Dr = sD + (m + 1) * 29;
            float* Cp = Cb0 + ((z + 1) * 26 + (y + 1)) * CROW + xq * 2;
#pragma unroll
            for (int g = 0; g < 9; g++) {
                float e = Do[3 * g] + Do[3 * g + 1];
                if (xq > 0)  e += Dl[3 * g + 2];
                float o = Do[3 * g + 1] + Do[3 * g + 2];
                if (xq < 23) o += Dr[3 * g];
                float2 v; v.x = e; v.y = o;
                *(float2*)(Cp + (size_t)g * CGRID) = v;
            }
        }
    }
}

// ============================================================
// Pass 2: one thread = one 2x2x2 octet. 25 LDG.64 (E,O pairs),
// then y- and z-parity collapse. All loads unconditional (halo).
// ============================================================
__global__ void __launch_bounds__(256) conv_pass2(const float* __restrict__ bias,
                                                  float* __restrict__ out) {
    int t = blockIdx.x * 256 + threadIdx.x;   // grid 864
    const int qx = t % 24; t /= 24;
    const int qy = t % 24; t /= 24;
    const int qz = t % 24;
    const int b  = t / 24;

    const float* __restrict__ Cb = g_C + (size_t)b * 9 * CGRID + qx * 2;

    const int wiT[5] = {2, 0, 1, 2, 0};
    const int dT[5]  = {0, 1, 1, 1, 2};      // halo-shifted pos delta

    // batch all 25 float2 loads (MLP)
    float2 v[25];
#pragma unroll
    for (int iz = 0; iz < 5; iz++) {
        const int zo = (qz + dT[iz]) * 26;
#pragma unroll
        for (int iy = 0; iy < 5; iy++) {
            const int g = wiT[iz] * 3 + wiT[iy];
            v[iz * 5 + iy] = __ldg((const float2*)(
                Cb + (size_t)g * CGRID + (zo + qy + dT[iy]) * CROW));
        }
    }

    // y-collapse then z-collapse
    float oE[2][2] = {{0,0},{0,0}};   // [pz][py] even-x outputs
    float oO[2][2] = {{0,0},{0,0}};   // [pz][py] odd-x outputs
#pragma unroll
    for (int iz = 0; iz < 5; iz++) {
        float yE0 = 0.f, yE1 = 0.f, yO0 = 0.f, yO1 = 0.f;
#pragma unroll
        for (int iy = 0; iy < 5; iy++) {
            const float e = v[iz * 5 + iy].x;
            const float o = v[iz * 5 + iy].y;
            if (iy <= 2) { yE0 += e; yO0 += o; }
            if (iy >= 2) { yE1 += e; yO1 += o; }
        }
        if (iz <= 2) { oE[0][0] += yE0; oE[0][1] += yE1; oO[0][0] += yO0; oO[0][1] += yO1; }
        if (iz >= 2) { oE[1][0] += yE0; oE[1][1] += yE1; oO[1][0] += yO0; oO[1][1] += yO1; }
    }

    const float bv = __ldg(bias);
    const int oz0 = 2 * qz, oy0 = 2 * qy, ox0 = 2 * qx;
#pragma unroll
    for (int pz = 0; pz < 2; pz++) {
        if (oz0 + pz >= ODIM) continue;
#pragma unroll
        for (int py = 0; py < 2; py++) {
            if (oy0 + py >= ODIM) continue;
            const long rbase = (((long)b * ODIM + oz0 + pz) * ODIM + oy0 + py) * ODIM;
            out[rbase + ox0] = (oE[pz][py] + bv) * 64.0f;
            if (ox0 + 1 < ODIM)
                out[rbase + ox0 + 1] = (oO[pz][py] + bv) * 64.0f;
        }
    }
}

extern "C" void kernel_launch(void* const* d_in, const int* in_sizes, int n_in,
                              void* d_out, int out_size) {
    const float* x    = (const float*)d_in[0];
    const float* w    = (const float*)d_in[1];
    const float* bias = (const float*)d_in[2];
    float* out = (float*)d_out;

    conv_pass1<<<NPOS / 288, 128>>>(x, w);      // 768 CTAs
    conv_pass2<<<NPOS / 256, 256>>>(bias, out); // 864 CTAs
}

// round 16
// speedup vs baseline: 1.1146x; 1.1146x over previous
#include <cuda_runtime.h>
#include <cuda_bf16.h>
#include <cstdint>

#define INC   64
#define DDIM  24
#define BATCH 16
#define DSP   (DDIM*DDIM*DDIM)      // 13824
#define NPOS  (BATCH*DSP)           // 221184
#define ODIM  47

// Collapsed-x array: C[b][g=wz*3+wy (9)][zh 26][yh 26][qx 24][par 2]
// z/y halo never written -> stays zero (.bss init).
#define CROW  48
#define CSL   (26*CROW)
#define CGRID (26*CSL)              // 32448 floats per (b,g)
#define CTOT  ((size_t)BATCH * 9 * CGRID)

__device__ float g_C[CTOT];

// ---------- helpers ----------
__device__ __forceinline__ uint32_t smem_u32(const void* p) {
    uint32_t a;
    asm("{ .reg .u64 t; cvta.to.shared.u64 t, %1; cvt.u32.u64 %0, t; }"
        : "=r"(a) : "l"(p));
    return a;
}
__device__ __forceinline__ uint32_t pack_bf(__nv_bfloat16 lo, __nv_bfloat16 hi) {
    return (uint32_t)__bfloat16_as_ushort(lo) | ((uint32_t)__bfloat16_as_ushort(hi) << 16);
}
__device__ __forceinline__ void ldsm_x4_t(uint32_t r[4], uint32_t addr) {
    asm volatile("ldmatrix.sync.aligned.m8n8.x4.trans.shared.b16 {%0,%1,%2,%3}, [%4];"
                 : "=r"(r[0]), "=r"(r[1]), "=r"(r[2]), "=r"(r[3]) : "r"(addr));
}
__device__ __forceinline__ void mma_bf16(float d[4], const uint32_t a[4],
                                         const uint32_t b0, const uint32_t b1) {
    asm volatile(
        "mma.sync.aligned.m16n8k16.row.col.f32.bf16.bf16.f32 "
        "{%0,%1,%2,%3}, {%4,%5,%6,%7}, {%8,%9}, {%0,%1,%2,%3};"
        : "+f"(d[0]), "+f"(d[1]), "+f"(d[2]), "+f"(d[3])
        : "r"(a[0]), "r"(a[1]), "r"(a[2]), "r"(a[3]), "r"(b0), "r"(b1));
}

#define SD_STRIDE 29

// ============================================================
// Pass 1: HMMA taps + in-smem x-collapse, software-pipelined.
// CTA = 128 thr, 384 positions = 16 full x-rows, 3 subtiles x 128.
// Per subtile: [MMA -> sD] sync [stage(s+1) || collapse(s)] sync.
// Boundary positions straddling subtiles deferred via 2-row carry.
// ============================================================
__global__ void __launch_bounds__(128, 3)
conv_pass1(const float* __restrict__ x, const float* __restrict__ w) {
    __shared__ __align__(16) char sA1[64 * 256];     // A1 split [k64][m128]
    __shared__ __align__(16) char sA2[64 * 256];     // A2 split
    __shared__ float sD[128 * SD_STRIDE];            // D[m][tap]
    __shared__ float carry[2][2][27];                // [buf][row 126/127][tap]
    const uint32_t sb1 = smem_u32(sA1);
    const uint32_t sb2 = smem_u32(sA2);

    const int tid  = threadIdx.x;
    const int lane = tid & 31;
    const int wid  = tid >> 5;

    // ---- W fragments (verbatim verified layout) ----
    uint32_t bw1[4][4][2], bw2[4][4][2];
    {
        const int n = lane >> 2;
#pragma unroll
        for (int nt = 0; nt < 4; nt++) {
            const int ng = nt * 8 + n;
            const bool nok = ng < 27;
#pragma unroll
            for (int j = 0; j < 4; j++) {
#pragma unroll
                for (int r = 0; r < 2; r++) {
                    const int c0 = j * 16 + (lane & 3) * 2 + r * 8;
                    const float va = nok ? __ldg(w + c0 * 1728 + ng) : 0.0f;
                    const float vb = nok ? __ldg(w + (c0 + 1) * 1728 + ng) : 0.0f;
                    const __nv_bfloat16 a1 = __float2bfloat16(va);
                    const __nv_bfloat16 a2 = __float2bfloat16(va - __bfloat162float(a1));
                    const __nv_bfloat16 b1 = __float2bfloat16(vb);
                    const __nv_bfloat16 b2 = __float2bfloat16(vb - __bfloat162float(b1));
                    bw1[nt][j][r] = pack_bf(a1, b1);
                    bw2[nt][j][r] = pack_bf(a2, b2);
                }
            }
        }
    }

    const int p0  = blockIdx.x * 384;        // grid 576; 384 | DSP
    const int b   = p0 / DSP;
    const int spb = p0 - b * DSP;
    const float* __restrict__ xb0 = x + (size_t)b * INC * DSP + spb;
    float* __restrict__ Cb0 = g_C + (size_t)b * 9 * CGRID;

    // ---- stage subtile s into sA1/sA2 (k-major, swizzled) ----
    auto stage = [&](int s) {
        const float* __restrict__ xb = xb0 + s * 128;
#pragma unroll 8
        for (int it = 0; it < 32; it++) {
            const int i  = it * 128 + tid;
            const int c  = i >> 6;
            const int m0 = (i & 63) * 2;     // warp: same c, consecutive m0
            const float2 xv = __ldg((const float2*)(xb + (size_t)c * DSP + m0));
            const __nv_bfloat16 h1a = __float2bfloat16(xv.x);
            const __nv_bfloat16 h2a = __float2bfloat16(xv.x - __bfloat162float(h1a));
            const __nv_bfloat16 h1b = __float2bfloat16(xv.y);
            const __nv_bfloat16 h2b = __float2bfloat16(xv.y - __bfloat162float(h1b));
            const int off = c * 256 + ((((m0 >> 3) ^ (c & 7)) << 4)) + ((m0 & 7) * 2);
            *(uint32_t*)(sA1 + off) = pack_bf(h1a, h1b);
            *(uint32_t*)(sA2 + off) = pack_bf(h2a, h2b);
        }
    };

    // ---- collapse one logical position l (of subtile s) ----
    auto collapse_one = [&](int s, int l) {
        const int cb = s & 1;
        const int m  = s * 128 + l;          // CTA-local position
        const int sp = spb + m;
        const int qx = m % 24;
        const int z  = sp / 576;
        const int rr = sp - z * 576;
        const int y  = rr / 24;
        float* Cp = Cb0 + ((z + 1) * 26 + (y + 1)) * CROW + qx * 2;

        // fetch rows l-1, l, l+1 through sD/carry
        const float* Dm = (l - 1 >= 0) ? &sD[(l - 1) * SD_STRIDE] : carry[cb][l + 1];
        const float* Do = (l     >= 0) ? &sD[ l      * SD_STRIDE] : carry[cb][1];
        const float* Dp = &sD[(l + 1) * SD_STRIDE];   // l+1 always >= 0
#pragma unroll
        for (int g = 0; g < 9; g++) {
            float e = Do[3 * g] + Do[3 * g + 1];
            if (qx > 0)  e += Dm[3 * g + 2];
            float o = Do[3 * g + 1] + Do[3 * g + 2];
            if (qx < 23) o += Dp[3 * g];
            float2 v; v.x = e; v.y = o;
            *(float2*)(Cp + (size_t)g * CGRID) = v;
        }
    };

    stage(0);
    __syncthreads();

    for (int s = 0; s < 3; s++) {
        // ---- MMA: warp wid does tiles 2*wid, 2*wid+1 (balanced) ----
#pragma unroll
        for (int ti = 0; ti < 2; ti++) {
            const int mb = (wid * 2 + ti) * 16;
            uint32_t fa1[4][4], fa2[4][4];
            const int sub = lane >> 3;
            const int mc  = mb + ((sub & 1) ? 8 : 0);
#pragma unroll
            for (int j = 0; j < 4; j++) {
                const int kr = j * 16 + ((sub & 2) ? 8 : 0) + (lane & 7);
                const uint32_t off = (uint32_t)(kr * 256 + (((mc >> 3) ^ (kr & 7)) << 4));
                ldsm_x4_t(fa1[j], sb1 + off);
                ldsm_x4_t(fa2[j], sb2 + off);
            }
            const int r0 = mb + (lane >> 2);
#pragma unroll
            for (int np = 0; np < 2; np++) {          // nt pairs: 2 indep chains
                const int ntA = np * 2, ntB = np * 2 + 1;
                float dA[4] = {0.f, 0.f, 0.f, 0.f};
                float dB[4] = {0.f, 0.f, 0.f, 0.f};
#pragma unroll
                for (int j = 0; j < 4; j++) {
                    mma_bf16(dA, fa1[j], bw1[ntA][j][0], bw1[ntA][j][1]);
                    mma_bf16(dB, fa1[j], bw1[ntB][j][0], bw1[ntB][j][1]);
                }
#pragma unroll
                for (int j = 0; j < 4; j++) {
                    mma_bf16(dA, fa1[j], bw2[ntA][j][0], bw2[ntA][j][1]);
                    mma_bf16(dB, fa1[j], bw2[ntB][j][0], bw2[ntB][j][1]);
                }
#pragma unroll
                for (int j = 0; j < 4; j++) {
                    mma_bf16(dA, fa2[j], bw1[ntA][j][0], bw1[ntA][j][1]);
                    mma_bf16(dB, fa2[j], bw1[ntB][j][0], bw1[ntB][j][1]);
                }
                const int tA0 = ntA * 8 + (lane & 3) * 2;
                const int tB0 = ntB * 8 + (lane & 3) * 2;
                if (tA0 < 27) {
                    sD[r0 * SD_STRIDE + tA0] = dA[0];
                    sD[(r0 + 8) * SD_STRIDE + tA0] = dA[2];
                    if (tA0 + 1 < 27) {
                        sD[r0 * SD_STRIDE + tA0 + 1] = dA[1];
                        sD[(r0 + 8) * SD_STRIDE + tA0 + 1] = dA[3];
                    }
                }
                if (tB0 < 27) {
                    sD[r0 * SD_STRIDE + tB0] = dB[0];
                    sD[(r0 + 8) * SD_STRIDE + tB0] = dB[2];
                    if (tB0 + 1 < 27) {
                        sD[r0 * SD_STRIDE + tB0 + 1] = dB[1];
                        sD[(r0 + 8) * SD_STRIDE + tB0 + 1] = dB[3];
                    }
                }
            }
        }
        __syncthreads();

        // ---- pipelined phase: stage(s+1) || collapse(s) + carry ----
        if (s < 2) stage(s + 1);             // disjoint smem (sA only)

        const int l = (s == 0) ? tid : tid - 1;
        if (s > 0 || tid < 127) collapse_one(s, l);
        if (s == 2 && tid == 127) collapse_one(s, 127);   // last position

        if (s < 2 && tid < 54) {             // carry rows 126,127 -> next buf
            const int li = tid / 27, t = tid - li * 27;
            carry[(s + 1) & 1][li][t] = sD[(126 + li) * SD_STRIDE + t];
        }
        __syncthreads();
    }
}

// ============================================================
// Pass 2: one thread = one 2x2x2 octet. 25 LDG.64 (E,O pairs),
// y/z parity collapse. Verified R13, unchanged.
// ============================================================
__global__ void __launch_bounds__(256) conv_pass2(const float* __restrict__ bias,
                                                  float* __restrict__ out) {
    int t = blockIdx.x * 256 + threadIdx.x;   // grid 864
    const int qx = t % 24; t /= 24;
    const int qy = t % 24; t /= 24;
    const int qz = t % 24;
    const int b  = t / 24;

    const float* __restrict__ Cb = g_C + (size_t)b * 9 * CGRID + qx * 2;

    const int wiT[5] = {2, 0, 1, 2, 0};
    const int dT[5]  = {0, 1, 1, 1, 2};

    float2 v[25];
#pragma unroll
    for (int iz = 0; iz < 5; iz++) {
        const int zo = (qz + dT[iz]) * 26;
#pragma unroll
        for (int iy = 0; iy < 5; iy++) {
            const int g = wiT[iz] * 3 + wiT[iy];
            v[iz * 5 + iy] = __ldg((const float2*)(
                Cb + (size_t)g * CGRID + (zo + qy + dT[iy]) * CROW));
        }
    }

    float oE[2][2] = {{0,0},{0,0}};
    float oO[2][2] = {{0,0},{0,0}};
#pragma unroll
    for (int iz = 0; iz < 5; iz++) {
        float yE0 = 0.f, yE1 = 0.f, yO0 = 0.f, yO1 = 0.f;
#pragma unroll
        for (int iy = 0; iy < 5; iy++) {
            const float e = v[iz * 5 + iy].x;
            const float o = v[iz * 5 + iy].y;
            if (iy <= 2) { yE0 += e; yO0 += o; }
            if (iy >= 2) { yE1 += e; yO1 += o; }
        }
        if (iz <= 2) { oE[0][0] += yE0; oE[0][1] += yE1; oO[0][0] += yO0; oO[0][1] += yO1; }
        if (iz >= 2) { oE[1][0] += yE0; oE[1][1] += yE1; oO[1][0] += yO0; oO[1][1] += yO1; }
    }

    const float bv = __ldg(bias);
    const int oz0 = 2 * qz, oy0 = 2 * qy, ox0 = 2 * qx;
#pragma unroll
    for (int pz = 0; pz < 2; pz++) {
        if (oz0 + pz >= ODIM) continue;
#pragma unroll
        for (int py = 0; py < 2; py++) {
            if (oy0 + py >= ODIM) continue;
            const long rbase = (((long)b * ODIM + oz0 + pz) * ODIM + oy0 + py) * ODIM;
            out[rbase + ox0] = (oE[pz][py] + bv) * 64.0f;
            if (ox0 + 1 < ODIM)
                out[rbase + ox0 + 1] = (oO[pz][py] + bv) * 64.0f;
        }
    }
}

extern "C" void kernel_launch(void* const* d_in, const int* in_sizes, int n_in,
                              void* d_out, int out_size) {
    const float* x    = (const float*)d_in[0];
    const float* w    = (const float*)d_in[1];
    const float* bias = (const float*)d_in[2];
    float* out = (float*)d_out;

    conv_pass1<<<NPOS / 384, 128>>>(x, w);      // 576 CTAs
    conv_pass2<<<NPOS / 256, 256>>>(bias, out); // 864 CTAs
}